// round 3
// baseline (speedup 1.0000x reference)
#include <cuda_runtime.h>
#include <math.h>

// Problem constants
#define Bn    2
#define Hh    64
#define Ww    2048
#define CINC  64
#define COUTC 64
#define CTOT  67           // 3 pn channels + 64 feature channels
#define NPIX  (Hh*Ww)      // 131072
#define NTOT  (Bn*NPIX)    // 262144

#define TILE    256
#define TW      258
#define THREADS 256

#define TILE_F  (CTOT*3*TW)            // 51858 floats
#define OFF_RNG (TILE_F)               // 3*TW floats
#define OFF_A   (TILE_F + 3*TW)        // 64*64 floats
#define SMEM_FLOATS (OFF_A + 64*64)    // 56728
#define SMEM_BYTES  (SMEM_FLOATS*4)    // 226912 B  (<= 227KB cap)

// ---- device scratch (no allocations allowed) ----
__device__ float  g_pre[(size_t)Bn*COUTC*NPIX];   // 64 MB pre-BN output, [b][o][n]
__device__ float  g_aggT[9*64*64];                // w_agg transposed to [k][c][o]
__device__ double g_sum[COUTC];
__device__ double g_sumsq[COUTC];
__device__ float  g_scale[COUTC];
__device__ float  g_shift[COUTC];

// ---------------------------------------------------------------------------
// Kernel 0: transpose w_agg [o][k*64+c] -> g_aggT [k][c][o]; zero stats.
// ---------------------------------------------------------------------------
__global__ void k_prep(const float* __restrict__ w_agg) {
    int idx = blockIdx.x * 256 + threadIdx.x;          // 0 .. 36863
    if (idx < 9*64*64) {
        int k = idx >> 12;          // /4096
        int c = (idx >> 6) & 63;
        int o = idx & 63;
        g_aggT[idx] = w_agg[o*576 + k*64 + c];
    }
    if (blockIdx.x == 0 && threadIdx.x < COUTC) {
        g_sum[threadIdx.x]   = 0.0;
        g_sumsq[threadIdx.x] = 0.0;
    }
}

// ---------------------------------------------------------------------------
// Kernel 1: fused dual-attention weighting + 576x64 projection per pixel.
// One CTA = 256 pixels of one image row. Output to g_pre [b][o][n].
// ---------------------------------------------------------------------------
__global__ void __launch_bounds__(THREADS, 1)
k_main(const float* __restrict__ x, const int* __restrict__ mask,
       const float* __restrict__ w_spatial, const float* __restrict__ b_spatial,
       const float* __restrict__ w_channel, const float* __restrict__ b_channel) {
    extern __shared__ float sm[];
    float* s_tile = sm;              // [67][3][258]
    float* s_rng  = sm + OFF_RNG;    // [3][258]
    float* s_A    = sm + OFF_A;      // [64 c][64 o] for current k

    const int tid = threadIdx.x;
    const int b  = blockIdx.z;
    const int h  = blockIdx.y;
    const int w0 = blockIdx.x * TILE;

    const float* xb = x + (size_t)b * CTOT * NPIX;

    // ---- load x tile (zero-padded halo) ----
    for (int idx = tid; idx < TILE_F; idx += THREADS) {
        int c   = idx / (3*TW);
        int rem = idx - c*(3*TW);
        int r   = rem / TW;
        int j   = rem - r*TW;
        int gh = h + r - 1;
        int gw = w0 + j - 1;
        float v = 0.f;
        if ((unsigned)gh < Hh && (unsigned)gw < Ww)
            v = xb[((size_t)c * Hh + gh) * Ww + gw];
        s_tile[idx] = v;
    }
    __syncthreads();

    // ---- rng = ||pn|| per tile position ----
    for (int idx = tid; idx < 3*TW; idx += THREADS) {
        float a = s_tile[idx];
        float bb = s_tile[3*TW*1 + idx];   // channel 1 offset = 1*774
        float cc = s_tile[3*TW*2 + idx];
        s_rng[idx] = sqrtf(a*a + bb*bb + cc*cc);
    }
    __syncthreads();

    // ---- per-thread pixel: geometry features ----
    const int jc = tid + 1;  // tile col of center
    float cx = s_tile[0*774 + 258 + jc];
    float cy = s_tile[1*774 + 258 + jc];
    float cz = s_tile[2*774 + 258 + jc];
    float cr = s_rng[258 + jc];

    float p0x[9], p0y[9], p0z[9], p0r[9];
    float mk[9];
    const int* mrow = mask + (size_t)b * NPIX;
    #pragma unroll
    for (int k = 0; k < 9; k++) {
        int r  = k / 3, dj = k % 3;
        int off = r*258 + tid + dj;
        p0x[k] = s_tile[off]         - cx;
        p0y[k] = s_tile[774 + off]   - cy;
        p0z[k] = s_tile[2*774 + off] - cz;
        p0r[k] = s_rng[off]          - cr;
        int gh = h + r - 1, gw = w0 + tid + dj - 1;
        mk[k] = ((unsigned)gh < Hh && (unsigned)gw < Ww) ? (float)mrow[gh*Ww + gw] : 0.f;
    }

    // ---- ws (max over c) / wc (max over k) ----
    float wsv[9];
    #pragma unroll
    for (int k = 0; k < 9; k++) wsv[k] = -1e30f;
    float wcp[64];                 // local memory (runtime-indexed later)
    float wcmax = -1e30f;

    const float4* wsp4 = (const float4*)w_spatial;
    const float4* wch4 = (const float4*)w_channel;
    #pragma unroll 4
    for (int c = 0; c < 64; c++) {
        float4 ws4 = __ldg(wsp4 + c);
        float4 wc4 = __ldg(wch4 + c);
        float bs = __ldg(b_spatial + c);
        float bc = __ldg(b_channel + c);
        float wcc = -1e30f;
        #pragma unroll
        for (int k = 0; k < 9; k++) {
            float ds = p0x[k]*ws4.x + p0y[k]*ws4.y + p0z[k]*ws4.z + p0r[k]*ws4.w + bs;
            float dc = p0x[k]*wc4.x + p0y[k]*wc4.y + p0z[k]*wc4.z + p0r[k]*wc4.w + bc;
            wsv[k] = fmaxf(wsv[k], ds);
            wcc    = fmaxf(wcc, dc);
        }
        wcp[c] = wcc;
        wcmax = fmaxf(wcmax, wcc);
    }

    // softmax over k (9)
    float wmax = wsv[0];
    #pragma unroll
    for (int k = 1; k < 9; k++) wmax = fmaxf(wmax, wsv[k]);
    float ssum = 0.f;
    #pragma unroll
    for (int k = 0; k < 9; k++) { wsv[k] = __expf(wsv[k] - wmax); ssum += wsv[k]; }
    float sinv = 1.f / ssum;
    float ak[9];
    #pragma unroll
    for (int k = 0; k < 9; k++) ak[k] = wsv[k] * sinv;

    // softmax over c (64), into local array
    float csum = 0.f;
    #pragma unroll 4
    for (int c = 0; c < 64; c++) { float e = __expf(wcp[c] - wcmax); wcp[c] = e; csum += e; }
    float cinv = 1.f / csum;
    #pragma unroll 4
    for (int c = 0; c < 64; c++) wcp[c] *= cinv;

    // ---- GEMM: out[o] = sum_{k,c} A[k][c][o] * (ak[k]+wcp[c])*mk[k]*feat[k][c]
    // acc packs output channel pairs (2i, 2i+1) as f32x2.
    unsigned long long acc[32];
    #pragma unroll
    for (int i = 0; i < 32; i++) acc[i] = 0ull;

    for (int k = 0; k < 9; k++) {
        __syncthreads();
        const float* Ak = g_aggT + k * 4096;
        #pragma unroll
        for (int t = 0; t < 16; t++)
            s_A[t*256 + tid] = Ak[t*256 + tid];
        __syncthreads();

        float akk = ak[k];
        float mkk = mk[k];
        int r = k / 3, dj = k % 3;
        const float* fbase = s_tile + 3*774 + r*258 + tid + dj;   // feat channel 0

        #pragma unroll 2
        for (int c = 0; c < 64; c++) {
            float w  = (akk + wcp[c]) * mkk;
            float fv = fbase[(size_t)c * 774];
            float wf = w * fv;
            unsigned long long wf2;
            asm("mov.b64 %0, {%1, %1};" : "=l"(wf2) : "f"(wf));
            const ulonglong2* a2 = (const ulonglong2*)(s_A + c*64);
            #pragma unroll
            for (int o = 0; o < 16; o++) {
                ulonglong2 av = a2[o];
                asm("fma.rn.f32x2 %0, %1, %2, %0;" : "+l"(acc[2*o])   : "l"(av.x), "l"(wf2));
                asm("fma.rn.f32x2 %0, %1, %2, %0;" : "+l"(acc[2*o+1]) : "l"(av.y), "l"(wf2));
            }
        }
    }

    // ---- write pre-BN output, channel-major ----
    size_t nidx = (size_t)h * Ww + w0 + tid;
    float* base = g_pre + (size_t)b * COUTC * NPIX + nidx;
    #pragma unroll
    for (int i = 0; i < 32; i++) {
        float lo, hi;
        asm("mov.b64 {%0, %1}, %2;" : "=f"(lo), "=f"(hi) : "l"(acc[i]));
        base[(size_t)(2*i)     * NPIX] = lo;
        base[(size_t)(2*i + 1) * NPIX] = hi;
    }
}

// ---------------------------------------------------------------------------
// Kernel 2: per-channel sum / sumsq over g_pre.
// grid = (64 channels, 16 slabs), 256 threads.
// ---------------------------------------------------------------------------
__global__ void k_stats() {
    int o = blockIdx.x, slab = blockIdx.y, tid = threadIdx.x;
    size_t base = (slab < 8)
        ? ((size_t)o * NPIX + (size_t)slab * 16384)
        : ((size_t)(COUTC + o) * NPIX + (size_t)(slab - 8) * 16384);
    const float4* p = (const float4*)(g_pre + base);
    float s = 0.f, s2 = 0.f;
    #pragma unroll 4
    for (int i = tid; i < 4096; i += 256) {
        float4 v = p[i];
        s  += v.x + v.y + v.z + v.w;
        s2 += v.x*v.x + v.y*v.y + v.z*v.z + v.w*v.w;
    }
    #pragma unroll
    for (int off = 16; off; off >>= 1) {
        s  += __shfl_down_sync(0xffffffffu, s,  off);
        s2 += __shfl_down_sync(0xffffffffu, s2, off);
    }
    __shared__ float rs[8], rq[8];
    int wrp = tid >> 5, lane = tid & 31;
    if (lane == 0) { rs[wrp] = s; rq[wrp] = s2; }
    __syncthreads();
    if (tid == 0) {
        float a = 0.f, q = 0.f;
        #pragma unroll
        for (int i = 0; i < 8; i++) { a += rs[i]; q += rq[i]; }
        atomicAdd(&g_sum[o],   (double)a);
        atomicAdd(&g_sumsq[o], (double)q);
    }
}

// ---------------------------------------------------------------------------
// Kernel 3: finalize BN scale/shift.
// ---------------------------------------------------------------------------
__global__ void k_final(const float* __restrict__ gamma, const float* __restrict__ beta) {
    int o = threadIdx.x;
    double N = (double)NTOT;
    double mean = g_sum[o] / N;
    double var  = g_sumsq[o] / N - mean * mean;
    if (var < 0.0) var = 0.0;
    float sc = gamma[o] * (float)(1.0 / sqrt(var + 1e-5));
    g_scale[o] = sc;
    g_shift[o] = beta[o] - (float)mean * sc;
}

// ---------------------------------------------------------------------------
// Kernel 4: normalize + ReLU -> d_out (layout identical to g_pre).
// ---------------------------------------------------------------------------
__global__ void k_norm(float* __restrict__ out) {
    int i = blockIdx.x * 256 + threadIdx.x;   // float4 index, exactly 4194304
    float4 v = ((const float4*)g_pre)[i];
    int o = (i >> 15) & 63;                   // 32768 float4 per channel slab
    float sc = g_scale[o], sh = g_shift[o];
    float4 r;
    r.x = fmaxf(0.f, v.x * sc + sh);
    r.y = fmaxf(0.f, v.y * sc + sh);
    r.z = fmaxf(0.f, v.z * sc + sh);
    r.w = fmaxf(0.f, v.w * sc + sh);
    ((float4*)out)[i] = r;
}

// ---------------------------------------------------------------------------
extern "C" void kernel_launch(void* const* d_in, const int* in_sizes, int n_in,
                              void* d_out, int out_size) {
    const float* x         = (const float*)d_in[0];
    const int*   mask      = (const int*)  d_in[1];
    const float* w_spatial = (const float*)d_in[2];
    const float* b_spatial = (const float*)d_in[3];
    const float* w_channel = (const float*)d_in[4];
    const float* b_channel = (const float*)d_in[5];
    const float* w_agg     = (const float*)d_in[6];
    const float* gamma     = (const float*)d_in[7];
    const float* beta      = (const float*)d_in[8];
    float* out = (float*)d_out;

    cudaFuncSetAttribute(k_main, cudaFuncAttributeMaxDynamicSharedMemorySize, SMEM_BYTES);

    k_prep<<<144, 256>>>(w_agg);
    dim3 grid(Ww / TILE, Hh, Bn);   // (8, 64, 2)
    k_main<<<grid, THREADS, SMEM_BYTES>>>(x, mask, w_spatial, b_spatial, w_channel, b_channel);
    k_stats<<<dim3(COUTC, 16), 256>>>();
    k_final<<<1, COUTC>>>(gamma, beta);
    k_norm<<<16384, 256>>>(out);
}

// round 4
// speedup vs baseline: 1.0046x; 1.0046x over previous
#include <cuda_runtime.h>
#include <math.h>

// Problem constants
#define Bn    2
#define Hh    64
#define Ww    2048
#define CINC  64
#define COUTC 64
#define CTOT  67           // 3 pn channels + 64 feature channels
#define NPIX  (Hh*Ww)      // 131072
#define NTOT  (Bn*NPIX)    // 262144

#define TILE    256
#define TW      258
#define THREADS 256

#define TILE_F  (CTOT*3*TW)            // 51858 floats
#define OFF_RNG (TILE_F)               // 3*TW floats
#define OFF_A   (TILE_F + 3*TW)        // 64*64 floats
#define SMEM_FLOATS (OFF_A + 64*64)    // 56728
#define SMEM_BYTES  (SMEM_FLOATS*4)    // 226912 B  (<= 227KB cap)

// ---- device scratch (no allocations allowed) ----
__device__ float  g_pre[(size_t)Bn*COUTC*NPIX];   // 64 MB pre-BN output, [b][o][n]
__device__ float  g_aggT[9*64*64];                // w_agg transposed to [k][c][o]
__device__ double g_sum[COUTC];
__device__ double g_sumsq[COUTC];
__device__ float  g_scale[COUTC];
__device__ float  g_shift[COUTC];

// ---------------------------------------------------------------------------
// Kernel 0: transpose w_agg [o][k*64+c] -> g_aggT [k][c][o]; zero stats.
// ---------------------------------------------------------------------------
__global__ void k_prep(const float* __restrict__ w_agg) {
    int idx = blockIdx.x * 256 + threadIdx.x;          // 0 .. 36863
    if (idx < 9*64*64) {
        int k = idx >> 12;          // /4096
        int c = (idx >> 6) & 63;
        int o = idx & 63;
        g_aggT[idx] = w_agg[o*576 + k*64 + c];
    }
    if (blockIdx.x == 0 && threadIdx.x < COUTC) {
        g_sum[threadIdx.x]   = 0.0;
        g_sumsq[threadIdx.x] = 0.0;
    }
}

// ---------------------------------------------------------------------------
// Kernel 1: fused dual-attention weighting + 576x64 projection per pixel.
// One CTA = 256 pixels of one image row. Output to g_pre [b][o][n].
// ---------------------------------------------------------------------------
__global__ void __launch_bounds__(THREADS, 1)
k_main(const float* __restrict__ x, const int* __restrict__ mask,
       const float* __restrict__ w_spatial, const float* __restrict__ b_spatial,
       const float* __restrict__ w_channel, const float* __restrict__ b_channel) {
    extern __shared__ float sm[];
    float* s_tile = sm;              // [67][3][258]
    float* s_rng  = sm + OFF_RNG;    // [3][258]
    float* s_A    = sm + OFF_A;      // [64 c][64 o] for current k

    const int tid = threadIdx.x;
    const int b  = blockIdx.z;
    const int h  = blockIdx.y;
    const int w0 = blockIdx.x * TILE;

    const float* xb = x + (size_t)b * CTOT * NPIX;

    // ---- load x tile (zero-padded halo) ----
    for (int idx = tid; idx < TILE_F; idx += THREADS) {
        int c   = idx / (3*TW);
        int rem = idx - c*(3*TW);
        int r   = rem / TW;
        int j   = rem - r*TW;
        int gh = h + r - 1;
        int gw = w0 + j - 1;
        float v = 0.f;
        if ((unsigned)gh < Hh && (unsigned)gw < Ww)
            v = xb[((size_t)c * Hh + gh) * Ww + gw];
        s_tile[idx] = v;
    }
    __syncthreads();

    // ---- rng = ||pn|| per tile position ----
    for (int idx = tid; idx < 3*TW; idx += THREADS) {
        float a = s_tile[idx];
        float bb = s_tile[3*TW*1 + idx];   // channel 1 offset = 1*774
        float cc = s_tile[3*TW*2 + idx];
        s_rng[idx] = sqrtf(a*a + bb*bb + cc*cc);
    }
    __syncthreads();

    // ---- per-thread pixel: geometry features ----
    const int jc = tid + 1;  // tile col of center
    float cx = s_tile[0*774 + 258 + jc];
    float cy = s_tile[1*774 + 258 + jc];
    float cz = s_tile[2*774 + 258 + jc];
    float cr = s_rng[258 + jc];

    float p0x[9], p0y[9], p0z[9], p0r[9];
    float mk[9];
    const int* mrow = mask + (size_t)b * NPIX;
    #pragma unroll
    for (int k = 0; k < 9; k++) {
        int r  = k / 3, dj = k % 3;
        int off = r*258 + tid + dj;
        p0x[k] = s_tile[off]         - cx;
        p0y[k] = s_tile[774 + off]   - cy;
        p0z[k] = s_tile[2*774 + off] - cz;
        p0r[k] = s_rng[off]          - cr;
        int gh = h + r - 1, gw = w0 + tid + dj - 1;
        mk[k] = ((unsigned)gh < Hh && (unsigned)gw < Ww) ? (float)mrow[gh*Ww + gw] : 0.f;
    }

    // ---- ws (max over c) / wc (max over k) ----
    float wsv[9];
    #pragma unroll
    for (int k = 0; k < 9; k++) wsv[k] = -1e30f;
    float wcp[64];                 // local memory (runtime-indexed later)
    float wcmax = -1e30f;

    const float4* wsp4 = (const float4*)w_spatial;
    const float4* wch4 = (const float4*)w_channel;
    #pragma unroll 4
    for (int c = 0; c < 64; c++) {
        float4 ws4 = __ldg(wsp4 + c);
        float4 wc4 = __ldg(wch4 + c);
        float bs = __ldg(b_spatial + c);
        float bc = __ldg(b_channel + c);
        float wcc = -1e30f;
        #pragma unroll
        for (int k = 0; k < 9; k++) {
            float ds = p0x[k]*ws4.x + p0y[k]*ws4.y + p0z[k]*ws4.z + p0r[k]*ws4.w + bs;
            float dc = p0x[k]*wc4.x + p0y[k]*wc4.y + p0z[k]*wc4.z + p0r[k]*wc4.w + bc;
            wsv[k] = fmaxf(wsv[k], ds);
            wcc    = fmaxf(wcc, dc);
        }
        wcp[c] = wcc;
        wcmax = fmaxf(wcmax, wcc);
    }

    // softmax over k (9)
    float wmax = wsv[0];
    #pragma unroll
    for (int k = 1; k < 9; k++) wmax = fmaxf(wmax, wsv[k]);
    float ssum = 0.f;
    #pragma unroll
    for (int k = 0; k < 9; k++) { wsv[k] = __expf(wsv[k] - wmax); ssum += wsv[k]; }
    float sinv = 1.f / ssum;
    float ak[9];
    #pragma unroll
    for (int k = 0; k < 9; k++) ak[k] = wsv[k] * sinv;

    // softmax over c (64), into local array
    float csum = 0.f;
    #pragma unroll 4
    for (int c = 0; c < 64; c++) { float e = __expf(wcp[c] - wcmax); wcp[c] = e; csum += e; }
    float cinv = 1.f / csum;
    #pragma unroll 4
    for (int c = 0; c < 64; c++) wcp[c] *= cinv;

    // ---- GEMM: out[o] = sum_{k,c} A[k][c][o] * (ak[k]+wcp[c])*mk[k]*feat[k][c]
    // acc packs output channel pairs (2i, 2i+1) as f32x2.
    unsigned long long acc[32];
    #pragma unroll
    for (int i = 0; i < 32; i++) acc[i] = 0ull;

    for (int k = 0; k < 9; k++) {
        __syncthreads();
        const float* Ak = g_aggT + k * 4096;
        #pragma unroll
        for (int t = 0; t < 16; t++)
            s_A[t*256 + tid] = Ak[t*256 + tid];
        __syncthreads();

        float akk = ak[k];
        float mkk = mk[k];
        int r = k / 3, dj = k % 3;
        const float* fbase = s_tile + 3*774 + r*258 + tid + dj;   // feat channel 0

        #pragma unroll 2
        for (int c = 0; c < 64; c++) {
            float w  = (akk + wcp[c]) * mkk;
            float fv = fbase[(size_t)c * 774];
            float wf = w * fv;
            unsigned long long wf2;
            asm("mov.b64 %0, {%1, %1};" : "=l"(wf2) : "f"(wf));
            const ulonglong2* a2 = (const ulonglong2*)(s_A + c*64);
            #pragma unroll
            for (int o = 0; o < 16; o++) {
                ulonglong2 av = a2[o];
                asm("fma.rn.f32x2 %0, %1, %2, %0;" : "+l"(acc[2*o])   : "l"(av.x), "l"(wf2));
                asm("fma.rn.f32x2 %0, %1, %2, %0;" : "+l"(acc[2*o+1]) : "l"(av.y), "l"(wf2));
            }
        }
    }

    // ---- write pre-BN output, channel-major ----
    size_t nidx = (size_t)h * Ww + w0 + tid;
    float* base = g_pre + (size_t)b * COUTC * NPIX + nidx;
    #pragma unroll
    for (int i = 0; i < 32; i++) {
        float lo, hi;
        asm("mov.b64 {%0, %1}, %2;" : "=f"(lo), "=f"(hi) : "l"(acc[i]));
        base[(size_t)(2*i)     * NPIX] = lo;
        base[(size_t)(2*i + 1) * NPIX] = hi;
    }
}

// ---------------------------------------------------------------------------
// Kernel 2: per-channel sum / sumsq over g_pre.
// grid = (64 channels, 16 slabs), 256 threads.
// ---------------------------------------------------------------------------
__global__ void k_stats() {
    int o = blockIdx.x, slab = blockIdx.y, tid = threadIdx.x;
    size_t base = (slab < 8)
        ? ((size_t)o * NPIX + (size_t)slab * 16384)
        : ((size_t)(COUTC + o) * NPIX + (size_t)(slab - 8) * 16384);
    const float4* p = (const float4*)(g_pre + base);
    float s = 0.f, s2 = 0.f;
    #pragma unroll 4
    for (int i = tid; i < 4096; i += 256) {
        float4 v = p[i];
        s  += v.x + v.y + v.z + v.w;
        s2 += v.x*v.x + v.y*v.y + v.z*v.z + v.w*v.w;
    }
    #pragma unroll
    for (int off = 16; off; off >>= 1) {
        s  += __shfl_down_sync(0xffffffffu, s,  off);
        s2 += __shfl_down_sync(0xffffffffu, s2, off);
    }
    __shared__ float rs[8], rq[8];
    int wrp = tid >> 5, lane = tid & 31;
    if (lane == 0) { rs[wrp] = s; rq[wrp] = s2; }
    __syncthreads();
    if (tid == 0) {
        float a = 0.f, q = 0.f;
        #pragma unroll
        for (int i = 0; i < 8; i++) { a += rs[i]; q += rq[i]; }
        atomicAdd(&g_sum[o],   (double)a);
        atomicAdd(&g_sumsq[o], (double)q);
    }
}

// ---------------------------------------------------------------------------
// Kernel 3: finalize BN scale/shift.
// ---------------------------------------------------------------------------
__global__ void k_final(const float* __restrict__ gamma, const float* __restrict__ beta) {
    int o = threadIdx.x;
    double N = (double)NTOT;
    double mean = g_sum[o] / N;
    double var  = g_sumsq[o] / N - mean * mean;
    if (var < 0.0) var = 0.0;
    float sc = gamma[o] * (float)(1.0 / sqrt(var + 1e-5));
    g_scale[o] = sc;
    g_shift[o] = beta[o] - (float)mean * sc;
}

// ---------------------------------------------------------------------------
// Kernel 4: normalize + ReLU -> d_out (layout identical to g_pre).
// ---------------------------------------------------------------------------
__global__ void k_norm(float* __restrict__ out) {
    int i = blockIdx.x * 256 + threadIdx.x;   // float4 index, exactly 4194304
    float4 v = ((const float4*)g_pre)[i];
    int o = (i >> 15) & 63;                   // 32768 float4 per channel slab
    float sc = g_scale[o], sh = g_shift[o];
    float4 r;
    r.x = fmaxf(0.f, v.x * sc + sh);
    r.y = fmaxf(0.f, v.y * sc + sh);
    r.z = fmaxf(0.f, v.z * sc + sh);
    r.w = fmaxf(0.f, v.w * sc + sh);
    ((float4*)out)[i] = r;
}

// ---------------------------------------------------------------------------
extern "C" void kernel_launch(void* const* d_in, const int* in_sizes, int n_in,
                              void* d_out, int out_size) {
    const float* x         = (const float*)d_in[0];
    const int*   mask      = (const int*)  d_in[1];
    const float* w_spatial = (const float*)d_in[2];
    const float* b_spatial = (const float*)d_in[3];
    const float* w_channel = (const float*)d_in[4];
    const float* b_channel = (const float*)d_in[5];
    const float* w_agg     = (const float*)d_in[6];
    const float* gamma     = (const float*)d_in[7];
    const float* beta      = (const float*)d_in[8];
    float* out = (float*)d_out;

    cudaFuncSetAttribute(k_main, cudaFuncAttributeMaxDynamicSharedMemorySize, SMEM_BYTES);

    k_prep<<<144, 256>>>(w_agg);
    dim3 grid(Ww / TILE, Hh, Bn);   // (8, 64, 2)
    k_main<<<grid, THREADS, SMEM_BYTES>>>(x, mask, w_spatial, b_spatial, w_channel, b_channel);
    k_stats<<<dim3(COUTC, 16), 256>>>();
    k_final<<<1, COUTC>>>(gamma, beta);
    k_norm<<<16384, 256>>>(out);
}

// round 6
// speedup vs baseline: 1.3710x; 1.3647x over previous
#include <cuda_runtime.h>
#include <math.h>
#include <stdint.h>

#define Bn    2
#define Hh    64
#define Ww    2048
#define COUTC 64
#define NPIX  (Hh*Ww)
#define NTOT  (Bn*NPIX)

#define TILE    256
#define TW      258
#define THREADS 256

// smem layout (float offsets)
#define S_PN   0                    // [3ch][3r][258] = 2322
#define S_RNG  2322                 // [3][258] = 774
#define S_A    3096                 // [64 c][64 o] = 4096
#define S_WCP  7192                 // [64 c][260 p] = 16640
#define S_W    23832                // [64 c][264 p] = 16896
#define S_A1   40728                // [9 k][260 p] = 2340  (ak*mk)
#define S_M    43068                // [9 k][260 p] = 2340  (mk)
#define SMEM_FLOATS 45408
#define SMEM_BYTES  (SMEM_FLOATS*4)   // 181632 B

__device__ float  g_pre[(size_t)Bn*COUTC*NPIX];   // [b][o][n]
__device__ float  g_aggT[9*64*64];                // [k][c][o]
__device__ double g_sum[COUTC];
__device__ double g_sumsq[COUTC];
__device__ float  g_scale[COUTC];
__device__ float  g_shift[COUTC];

__global__ void k_prep(const float* __restrict__ w_agg) {
    int idx = blockIdx.x * 256 + threadIdx.x;
    if (idx < 9*64*64) {
        int k = idx >> 12, c = (idx >> 6) & 63, o = idx & 63;
        g_aggT[idx] = w_agg[o*576 + k*64 + c];
    }
    if (blockIdx.x == 0 && threadIdx.x < COUTC) {
        g_sum[threadIdx.x] = 0.0; g_sumsq[threadIdx.x] = 0.0;
    }
}

__global__ void __launch_bounds__(THREADS, 1)
k_main(const float* __restrict__ x, const int* __restrict__ mask,
       const float* __restrict__ w_spatial, const float* __restrict__ b_spatial,
       const float* __restrict__ w_channel, const float* __restrict__ b_channel) {
    extern __shared__ float sm[];
    const int tid = threadIdx.x;
    const int pg  = tid & 31;      // pixel group: pixels [pg*8, pg*8+8)
    const int og  = tid >> 5;      // output group: outputs [og*8, og*8+8)
    const int b = blockIdx.z, h = blockIdx.y, w0 = blockIdx.x * TILE;

    const float* xb = x + (size_t)b * 67 * NPIX;

    // ---- pn tile (3 ch, 3 rows, halo) ----
    for (int idx = tid; idx < 3*3*TW; idx += THREADS) {
        int c = idx/(3*TW), rem = idx - c*3*TW, r = rem/TW, j = rem - r*TW;
        int gh = h + r - 1, gw = w0 + j - 1;
        float v = 0.f;
        if ((unsigned)gh < Hh && (unsigned)gw < Ww) v = xb[((size_t)c*Hh + gh)*Ww + gw];
        sm[S_PN + idx] = v;
    }
    __syncthreads();
    for (int idx = tid; idx < 3*TW; idx += THREADS) {
        float a = sm[S_PN+idx], bb = sm[S_PN+3*TW+idx], cc = sm[S_PN+6*TW+idx];
        sm[S_RNG + idx] = sqrtf(a*a + bb*bb + cc*cc);
    }
    __syncthreads();

    // ---- attention: thread = pixel tid ----
    {
        const int p = tid, jc = p + 1;
        float cx = sm[S_PN + TW + jc];
        float cy = sm[S_PN + 3*TW + TW + jc];
        float cz = sm[S_PN + 6*TW + TW + jc];
        float cr = sm[S_RNG + TW + jc];
        float p0x[9], p0y[9], p0z[9], p0r[9], mk[9];
        const int* mrow = mask + (size_t)b * NPIX;
        #pragma unroll
        for (int k = 0; k < 9; k++) {
            int r = k/3, dj = k - r*3, off = r*TW + p + dj;
            p0x[k] = sm[S_PN + off]        - cx;
            p0y[k] = sm[S_PN + 3*TW + off] - cy;
            p0z[k] = sm[S_PN + 6*TW + off] - cz;
            p0r[k] = sm[S_RNG + off]       - cr;
            int gh = h + r - 1, gw = w0 + p + dj - 1;
            mk[k] = ((unsigned)gh < Hh && (unsigned)gw < Ww) ? (float)mrow[gh*Ww + gw] : 0.f;
        }
        float wsv[9];
        #pragma unroll
        for (int k = 0; k < 9; k++) wsv[k] = -1e30f;
        float wcp[64], wcmax = -1e30f;
        #pragma unroll
        for (int c = 0; c < 64; c++) {
            float4 w4 = __ldg((const float4*)w_spatial + c);
            float4 v4 = __ldg((const float4*)w_channel + c);
            float bs = __ldg(b_spatial + c), bc = __ldg(b_channel + c);
            float wcc = -1e30f;
            #pragma unroll
            for (int k = 0; k < 9; k++) {
                float ds = fmaf(p0x[k], w4.x, fmaf(p0y[k], w4.y, fmaf(p0z[k], w4.z, fmaf(p0r[k], w4.w, bs))));
                float dc = fmaf(p0x[k], v4.x, fmaf(p0y[k], v4.y, fmaf(p0z[k], v4.z, fmaf(p0r[k], v4.w, bc))));
                wsv[k] = fmaxf(wsv[k], ds);
                wcc    = fmaxf(wcc, dc);
            }
            wcp[c] = wcc;
            wcmax = fmaxf(wcmax, wcc);
        }
        float wmax = wsv[0];
        #pragma unroll
        for (int k = 1; k < 9; k++) wmax = fmaxf(wmax, wsv[k]);
        float ssum = 0.f;
        #pragma unroll
        for (int k = 0; k < 9; k++) { wsv[k] = __expf(wsv[k] - wmax); ssum += wsv[k]; }
        float sinv = 1.f / ssum;
        float csum = 0.f;
        #pragma unroll
        for (int c = 0; c < 64; c++) { float e = __expf(wcp[c] - wcmax); wcp[c] = e; csum += e; }
        float cinv = 1.f / csum;
        #pragma unroll
        for (int k = 0; k < 9; k++) {
            sm[S_A1 + k*260 + p] = wsv[k]*sinv*mk[k];
            sm[S_M  + k*260 + p] = mk[k];
        }
        #pragma unroll
        for (int c = 0; c < 64; c++) sm[S_WCP + c*260 + p] = wcp[c]*cinv;
    }

    // ---- GEMM: register-blocked 8 pixels x 8 outputs per thread ----
    unsigned long long acc[32];   // [pix 0..7][opair 0..3]
    #pragma unroll
    for (int i = 0; i < 32; i++) acc[i] = 0ull;

    for (int k9 = 0; k9 < 9; k9++) {
        __syncthreads();   // previous k's s_A/s_W reads complete
        // stage A[k9] (64x64)
        {
            const float4* src = (const float4*)(g_aggT + k9*4096);
            float4* dst = (float4*)(sm + S_A);
            #pragma unroll
            for (int t = 0; t < 4; t++) dst[t*256 + tid] = src[t*256 + tid];
        }
        // materialize W[c][p] for own pixel p = tid
        {
            const int rr = k9/3, dj = k9 - rr*3;
            const int gh = h + rr - 1, gw = w0 + tid + dj - 1;
            const bool valid = ((unsigned)gh < Hh) && ((unsigned)gw < Ww);
            const float* fptr = xb + (size_t)3*NPIX + (size_t)gh*Ww + gw;
            float amk = sm[S_A1 + k9*260 + tid];
            float mkk = sm[S_M  + k9*260 + tid];
            #pragma unroll 8
            for (int c = 0; c < 64; c++) {
                float fv = valid ? __ldg(fptr + (size_t)c*NPIX) : 0.f;
                float wf = fmaf(mkk, sm[S_WCP + c*260 + tid], amk) * fv;
                sm[S_W + c*264 + tid] = wf;
            }
        }
        __syncthreads();

        #pragma unroll 2
        for (int c = 0; c < 64; c++) {
            const float* wr = sm + S_W + c*264 + pg*8;
            float4 wa = *(const float4*)wr;
            float4 wb = *(const float4*)(wr + 4);
            const unsigned long long* ar = (const unsigned long long*)(sm + S_A + c*64 + og*8);
            unsigned long long a0 = ar[0], a1 = ar[1], a2 = ar[2], a3 = ar[3];
            #define DO_PIX(i, wv) { \
                unsigned long long wf2; \
                asm("mov.b64 %0, {%1, %1};" : "=l"(wf2) : "f"(wv)); \
                asm("fma.rn.f32x2 %0, %1, %2, %0;" : "+l"(acc[(i)*4+0]) : "l"(a0), "l"(wf2)); \
                asm("fma.rn.f32x2 %0, %1, %2, %0;" : "+l"(acc[(i)*4+1]) : "l"(a1), "l"(wf2)); \
                asm("fma.rn.f32x2 %0, %1, %2, %0;" : "+l"(acc[(i)*4+2]) : "l"(a2), "l"(wf2)); \
                asm("fma.rn.f32x2 %0, %1, %2, %0;" : "+l"(acc[(i)*4+3]) : "l"(a3), "l"(wf2)); }
            DO_PIX(0, wa.x) DO_PIX(1, wa.y) DO_PIX(2, wa.z) DO_PIX(3, wa.w)
            DO_PIX(4, wb.x) DO_PIX(5, wb.y) DO_PIX(6, wb.z) DO_PIX(7, wb.w)
            #undef DO_PIX
        }
    }

    // ---- epilogue: stage [o][p] in s_W, then coalesced store ----
    __syncthreads();
    #pragma unroll
    for (int i = 0; i < 8; i++) {
        #pragma unroll
        for (int j = 0; j < 4; j++) {
            float lo, hi;
            asm("mov.b64 {%0, %1}, %2;" : "=f"(lo), "=f"(hi) : "l"(acc[i*4+j]));
            sm[S_W + (og*8 + 2*j    )*264 + pg*8 + i] = lo;
            sm[S_W + (og*8 + 2*j + 1)*264 + pg*8 + i] = hi;
        }
    }
    __syncthreads();
    {
        const size_t n0 = (size_t)h * Ww + w0;
        float* gp = g_pre + (size_t)b * COUTC * NPIX;
        #pragma unroll
        for (int t = 0; t < 16; t++) {
            int idx = t*256 + tid;        // 0..4095 float4s
            int o = idx >> 6, p4 = idx & 63;
            float4 v = *(const float4*)&sm[S_W + o*264 + p4*4];
            *(float4*)(gp + (size_t)o*NPIX + n0 + p4*4) = v;
        }
    }
}

__global__ void k_stats() {
    int o = blockIdx.x, slab = blockIdx.y, tid = threadIdx.x;
    size_t base = (slab < 8)
        ? ((size_t)o * NPIX + (size_t)slab * 16384)
        : ((size_t)(COUTC + o) * NPIX + (size_t)(slab - 8) * 16384);
    const float4* p = (const float4*)(g_pre + base);
    float s = 0.f, s2 = 0.f;
    #pragma unroll 4
    for (int i = tid; i < 4096; i += 256) {
        float4 v = p[i];
        s  += v.x + v.y + v.z + v.w;
        s2 += v.x*v.x + v.y*v.y + v.z*v.z + v.w*v.w;
    }
    #pragma unroll
    for (int off = 16; off; off >>= 1) {
        s  += __shfl_down_sync(0xffffffffu, s,  off);
        s2 += __shfl_down_sync(0xffffffffu, s2, off);
    }
    __shared__ float rs[8], rq[8];
    int wrp = tid >> 5, lane = tid & 31;
    if (lane == 0) { rs[wrp] = s; rq[wrp] = s2; }
    __syncthreads();
    if (tid == 0) {
        float a = 0.f, q = 0.f;
        #pragma unroll
        for (int i = 0; i < 8; i++) { a += rs[i]; q += rq[i]; }
        atomicAdd(&g_sum[o],   (double)a);
        atomicAdd(&g_sumsq[o], (double)q);
    }
}

__global__ void k_final(const float* __restrict__ gamma, const float* __restrict__ beta) {
    int o = threadIdx.x;
    double N = (double)NTOT;
    double mean = g_sum[o] / N;
    double var  = g_sumsq[o] / N - mean * mean;
    if (var < 0.0) var = 0.0;
    float sc = gamma[o] * (float)(1.0 / sqrt(var + 1e-5));
    g_scale[o] = sc;
    g_shift[o] = beta[o] - (float)mean * sc;
}

__global__ void k_norm(float* __restrict__ out) {
    int i = blockIdx.x * 256 + threadIdx.x;
    float4 v = ((const float4*)g_pre)[i];
    int o = (i >> 15) & 63;
    float sc = g_scale[o], sh = g_shift[o];
    float4 r;
    r.x = fmaxf(0.f, v.x * sc + sh);
    r.y = fmaxf(0.f, v.y * sc + sh);
    r.z = fmaxf(0.f, v.z * sc + sh);
    r.w = fmaxf(0.f, v.w * sc + sh);
    ((float4*)out)[i] = r;
}

extern "C" void kernel_launch(void* const* d_in, const int* in_sizes, int n_in,
                              void* d_out, int out_size) {
    const float* x         = (const float*)d_in[0];
    const int*   mask      = (const int*)  d_in[1];
    const float* w_spatial = (const float*)d_in[2];
    const float* b_spatial = (const float*)d_in[3];
    const float* w_channel = (const float*)d_in[4];
    const float* b_channel = (const float*)d_in[5];
    const float* w_agg     = (const float*)d_in[6];
    const float* gamma     = (const float*)d_in[7];
    const float* beta      = (const float*)d_in[8];
    float* out = (float*)d_out;

    cudaFuncSetAttribute(k_main, cudaFuncAttributeMaxDynamicSharedMemorySize, SMEM_BYTES);

    k_prep<<<144, 256>>>(w_agg);
    dim3 grid(Ww / TILE, Hh, Bn);   // (8, 64, 2)
    k_main<<<grid, THREADS, SMEM_BYTES>>>(x, mask, w_spatial, b_spatial, w_channel, b_channel);
    k_stats<<<dim3(COUTC, 16), 256>>>();
    k_final<<<1, COUTC>>>(gamma, beta);
    k_norm<<<16384, 256>>>(out);
}